// round 11
// baseline (speedup 1.0000x reference)
#include <cuda_runtime.h>
#include <cuda_fp16.h>
#include <cstdint>

#define HID 128
#define DT_MAXF 0.125f
#define NSTEPS 8
#define THREADS 512
#define MAXN (1<<18)
#define APITCH 272              // bytes per A row (128 fp16 data + pad)

__device__ int g_parts[1024][16];
__device__ int g_cursor[16];
__device__ int g_perm[MAXN];

// ---- smem byte offsets ----
#define OFF_AHI  0              // 34816: A hi fp16 [128][136]
#define OFF_ALO  34816          // 34816: A lo fp16 [128][136]
#define OFF_PSUM 69632          // 24576: psum f32 [16 warps][128 m][3]
#define OFF_W1X  94208          // 2048 : f32 [k][4] = W1[64+q][k]
#define SMEM_BYTES 96256

#define FPSUM (OFF_PSUM/4)
#define FW1X  (OFF_W1X/4)

__device__ __forceinline__ float ftanh(float x){
    float e = __expf(2.0f*x);
    return 1.0f - __fdividef(2.0f, e+1.0f);
}
__device__ __forceinline__ uint32_t packh(float a, float b){
    __half2 t = __floats2half2_rn(a, b);
    return *reinterpret_cast<uint32_t*>(&t);
}
__device__ __forceinline__ void splith(float v, float& hi, float& lo){
    hi = __half2float(__float2half_rn(v));
    lo = v - hi;
}
__device__ __forceinline__ void mma16816(float d[4], const uint32_t a[4], const uint32_t b[2]){
    asm volatile(
        "mma.sync.aligned.m16n8k16.row.col.f32.f16.f16.f32 "
        "{%0,%1,%2,%3}, {%4,%5,%6,%7}, {%8,%9}, {%0,%1,%2,%3};"
        : "+f"(d[0]), "+f"(d[1]), "+f"(d[2]), "+f"(d[3])
        : "r"(a[0]), "r"(a[1]), "r"(a[2]), "r"(a[3]), "r"(b[0]), "r"(b[1]));
}
__device__ __forceinline__ void ldmat4(uint32_t a[4], uint32_t addr){
    asm volatile("ldmatrix.sync.aligned.m8n8.x4.shared.b16 {%0,%1,%2,%3}, [%4];"
        : "=r"(a[0]), "=r"(a[1]), "=r"(a[2]), "=r"(a[3]) : "r"(addr) : "memory");
}

// One GEMM phase + fused epilogue. Each warp: all 128 rows x its 8 cols.
// 2-term fp16 split with INDEPENDENT hi/lo accumulator chains (2x MMA ILP).
// MODE 0: v-epi tanh(d+b2)*W3 ; MODE 1: same + capture g2 ; MODE 2: (d*g2)*W3
template<int MODE>
__device__ __forceinline__ void gemm_epi(float* smf, uint32_t sb,
        int lane, int tig, int g, int wslot,
        const uint32_t (&bhh)[8][2],
        uint32_t (&g2p)[8][2], const float (&b2r)[2], const float (&w3r)[2][3])
{
    const uint32_t arow = sb + (uint32_t)(lane & 15)*APITCH + ((lane & 16) ? 16u : 0u);
#pragma unroll
    for (int mt = 0; mt < 8; mt++){
        uint32_t ab = arow + (uint32_t)(mt*16)*APITCH;
        float d[4] = {0.f,0.f,0.f,0.f};
        float e[4] = {0.f,0.f,0.f,0.f};
#pragma unroll
        for (int kt = 0; kt < 8; kt++){
            uint32_t ah[4], al[4];
            ldmat4(ah, ab + kt*32);
            ldmat4(al, ab + 34816u + kt*32);
            mma16816(d, ah, bhh[kt]);
            mma16816(e, al, bhh[kt]);
        }
#pragma unroll
        for (int q = 0; q < 4; q++) d[q] += e[q];
        float s[2][3] = {{0.f,0.f,0.f},{0.f,0.f,0.f}};
#pragma unroll
        for (int rh = 0; rh < 2; rh++){
            float g2v[2] = {0.f, 0.f};
            if (MODE == 2){
                uint32_t u = g2p[mt][rh];
                __half2 hv2 = *reinterpret_cast<__half2*>(&u);
                g2v[0] = __low2float(hv2); g2v[1] = __high2float(hv2);
            }
            float ng[2] = {0.f, 0.f};
#pragma unroll
            for (int cj = 0; cj < 2; cj++){
                float val = d[rh*2 + cj];
                float use;
                if (MODE < 2){
                    float hv = ftanh(val + b2r[cj]);
                    if (MODE == 1) ng[cj] = fmaf(-hv, hv, 1.f);
                    use = hv;
                } else {
                    use = val * g2v[cj];
                }
                s[rh][0] = fmaf(use, w3r[cj][0], s[rh][0]);
                s[rh][1] = fmaf(use, w3r[cj][1], s[rh][1]);
                s[rh][2] = fmaf(use, w3r[cj][2], s[rh][2]);
            }
            if (MODE == 1){
                __half2 p = __floats2half2_rn(ng[0], ng[1]);
                g2p[mt][rh] = *reinterpret_cast<uint32_t*>(&p);
            }
        }
#pragma unroll
        for (int rh = 0; rh < 2; rh++)
#pragma unroll
        for (int o = 0; o < 3; o++){
            float v = s[rh][o];
            v += __shfl_xor_sync(0xffffffffu, v, 1);
            v += __shfl_xor_sync(0xffffffffu, v, 2);
            s[rh][o] = v;
        }
        if (tig == 0){
            float* p0 = smf + FPSUM + wslot*384 + (mt*16 + g)*3;
            p0[0]=s[0][0]; p0[1]=s[0][1]; p0[2]=s[0][2];
            float* p1 = p0 + 8*3;
            p1[0]=s[1][0]; p1[1]=s[1][1]; p1[2]=s[1][2];
        }
    }
}

// ---- bucketing: 3 kernels, no zero pass (partials are overwritten) ----
__device__ __forceinline__ int steps_needed(float off){
    float a = fabsf(off);
    int k = (int)ceilf(a*8.0f);
    return k > NSTEPS ? NSTEPS : k;
}
__global__ void k_hist(const float* t1, const float* t2, int n){
    __shared__ int lh[16];
    if (threadIdx.x < 16) lh[threadIdx.x] = 0;
    __syncthreads();
    int i = blockIdx.x*blockDim.x + threadIdx.x;
    if (i < n) atomicAdd(&lh[steps_needed(t1[i]-t2[i])], 1);
    __syncthreads();
    if (threadIdx.x < 16) g_parts[blockIdx.x][threadIdx.x] = lh[threadIdx.x];
}
__global__ void k_prefix(int nb){
    __shared__ int tot[16];
    int b = threadIdx.x;
    if (b < 16){
        int s = 0;
        for (int blk = 0; blk < nb; blk++) s += g_parts[blk][b];
        tot[b] = s;
    }
    __syncthreads();
    if (threadIdx.x == 0){
        int s = 0;
#pragma unroll
        for (int q = 0; q <= NSTEPS; q++){ g_cursor[q] = s; s += tot[q]; }
    }
}
__global__ void k_scatter(const float* t1, const float* t2, int n){
    __shared__ int lh[16], lb[16];
    if (threadIdx.x < 16) lh[threadIdx.x] = 0;
    __syncthreads();
    int i = blockIdx.x*blockDim.x + threadIdx.x;
    int k = 0, loc = 0; bool v = (i < n);
    if (v){ k = steps_needed(t1[i]-t2[i]); loc = atomicAdd(&lh[k], 1); }
    __syncthreads();
    if (threadIdx.x < 16 && lh[threadIdx.x])
        lb[threadIdx.x] = atomicAdd(&g_cursor[threadIdx.x], lh[threadIdx.x]);
    __syncthreads();
    if (v) g_perm[lb[k]+loc] = i;
}

__global__ void __launch_bounds__(THREADS, 1)
velwarp_kernel(const float* __restrict__ code_g, const float* __restrict__ pos_g,
               const float* __restrict__ t1_g, const float* __restrict__ t2_g,
               const float* __restrict__ W1_g, const float* __restrict__ b1_g,
               const float* __restrict__ W2_g, const float* __restrict__ b2_g,
               const float* __restrict__ W3_g, const float* __restrict__ b3_g,
               float* __restrict__ out, int n)
{
    extern __shared__ char smc[];
    float* smf = (float*)smc;
    uint32_t sb;
    asm("{ .reg .u64 t; cvta.to.shared.u64 t, %1; cvt.u32.u64 %0, t; }" : "=r"(sb) : "l"(smc));

    const int tid  = threadIdx.x;
    const int lane = tid & 31;
    const int g    = lane >> 2;
    const int tig  = lane & 3;
    const int wslot = tid >> 5;          // 0..15; warp owns output cols 8w..8w+7
    const int nbase = wslot * 8;
    const int m    = tid & 127;          // point in CTA
    const int kq   = tid >> 7;           // k-quarter 0..3
    const int kb   = kq * 32;
    const int pbase = blockIdx.x * 128;
    const int slot = pbase + m;
    const int myp = (slot < n) ? g_perm[slot] : -1;

    // ---- prologue: W1 (f32) staged temporarily into A region ----
    float cp[32];   // cpre for (m, kb..kb+31) — lives in registers
    {
        float* w1tmp = (float*)(smc + OFF_AHI);
        for (int i = tid; i < 64*HID; i += THREADS) w1tmp[i] = W1_g[i];
        if (tid < HID){
#pragma unroll
            for (int kk=0;kk<4;kk++) smf[FW1X + tid*4 + kk] = W1_g[(64+kk)*HID + tid];
        }
        __syncthreads();
#pragma unroll
        for (int i=0;i<32;i++) cp[i] = b1_g[kb+i];
#pragma unroll 1
        for (int c0=0;c0<64;c0+=16){
            float cd[16];
#pragma unroll
            for (int u=0;u<16;u++)
                cd[u] = (myp>=0) ? code_g[(size_t)myp*64 + c0 + u] : 0.f;
#pragma unroll
            for (int u=0;u<16;u++){
                float cc = cd[u];
                const float* wr = w1tmp + (c0+u)*HID + kb;
#pragma unroll
                for (int i=0;i<32;i+=4){
                    float4 w = *(const float4*)(wr + i);
                    cp[i]   = fmaf(cc,w.x,cp[i]);
                    cp[i+1] = fmaf(cc,w.y,cp[i+1]);
                    cp[i+2] = fmaf(cc,w.z,cp[i+2]);
                    cp[i+3] = fmaf(cc,w.w,cp[i+3]);
                }
            }
        }
        __syncthreads();   // A region free from here
    }

    // ---- W2 hi fragments (fp16) in registers: this warp's 8 cols ----
    uint32_t bhh[8][2];
#pragma unroll
    for (int kt=0;kt<8;kt++){
        int nn = nbase + g;
        int k0 = kt*16 + tig*2;
        float f0=W2_g[(size_t)k0*HID+nn],     f1=W2_g[(size_t)(k0+1)*HID+nn];
        float f2=W2_g[(size_t)(k0+8)*HID+nn], f3=W2_g[(size_t)(k0+9)*HID+nn];
        bhh[kt][0]=packh(f0,f1); bhh[kt][1]=packh(f2,f3);
    }
    float b2r[2], w3r[2][3];
#pragma unroll
    for (int cj=0;cj<2;cj++){
        int nn = nbase + tig*2 + cj;
        b2r[cj] = b2_g[nn];
        w3r[cj][0]=W3_g[nn*3+0]; w3r[cj][1]=W3_g[nn*3+1]; w3r[cj][2]=W3_g[nn*3+2];
    }
    const float b3x=b3_g[0], b3y=b3_g[1], b3z=b3_g[2];

    // ---- ODE state: REPLICATED in all 4 k-quarter threads per point ----
    float px=0.f,py=0.f,pz=0.f,tt=0.f,off=0.f;
    float D[9] = {1,0,0, 0,1,0, 0,0,1};
    if (myp>=0){
        px = pos_g[(size_t)myp*3+0];
        py = pos_g[(size_t)myp*3+1];
        pz = pos_g[(size_t)myp*3+2];
        tt = t1_g[myp];
        off = tt - t2_g[myp];
    }

    float h[32];
    uint32_t g2p[8][2];

#define LAYER1_STAGE(X0,X1,X2,X3) do { \
        _Pragma("unroll") \
        for (int i2=0;i2<4;i2++){ \
            uint32_t hi4[4], lo4[4]; \
            _Pragma("unroll") \
            for (int u2=0;u2<4;u2++){ \
                float hv0, hv1; \
                { int i=i2*8+u2*2;   float a=cp[i]; \
                  float4 w=*(const float4*)(smf+FW1X+(kb+i)*4); \
                  a=fmaf((X0),w.x,a); a=fmaf((X1),w.y,a); a=fmaf((X2),w.z,a); a=fmaf((X3),w.w,a); \
                  hv0=ftanh(a); h[i]=hv0; } \
                { int i=i2*8+u2*2+1; float a=cp[i]; \
                  float4 w=*(const float4*)(smf+FW1X+(kb+i)*4); \
                  a=fmaf((X0),w.x,a); a=fmaf((X1),w.y,a); a=fmaf((X2),w.z,a); a=fmaf((X3),w.w,a); \
                  hv1=ftanh(a); h[i]=hv1; } \
                float ha,la,hb,lb; splith(hv0,ha,la); splith(hv1,hb,lb); \
                hi4[u2]=packh(ha,hb); lo4[u2]=packh(la,lb); \
            } \
            *(uint4*)(smc + OFF_AHI + m*APITCH + (kb+i2*8)*2) = make_uint4(hi4[0],hi4[1],hi4[2],hi4[3]); \
            *(uint4*)(smc + OFF_ALO + m*APITCH + (kb+i2*8)*2) = make_uint4(lo4[0],lo4[1],lo4[2],lo4[3]); \
        } \
    } while(0)

#define STAGE_TAN(J) do { \
        _Pragma("unroll") \
        for (int i2=0;i2<4;i2++){ \
            uint32_t hi4[4], lo4[4]; \
            _Pragma("unroll") \
            for (int u2=0;u2<4;u2++){ \
                int i = i2*8+u2*2; \
                float v0 = h[i]   * smf[FW1X + (kb+i)*4   + (J)]; \
                float v1 = h[i+1] * smf[FW1X + (kb+i+1)*4 + (J)]; \
                float ha,la,hb,lb; splith(v0,ha,la); splith(v1,hb,lb); \
                hi4[u2]=packh(ha,hb); lo4[u2]=packh(la,lb); \
            } \
            *(uint4*)(smc + OFF_AHI + m*APITCH + (kb+i2*8)*2) = make_uint4(hi4[0],hi4[1],hi4[2],hi4[3]); \
            *(uint4*)(smc + OFF_ALO + m*APITCH + (kb+i2*8)*2) = make_uint4(lo4[0],lo4[1],lo4[2],lo4[3]); \
        } \
    } while(0)

#define SUM3(r0,r1,r2) do { r0=0.f;r1=0.f;r2=0.f; \
        _Pragma("unroll") \
        for (int ww=0;ww<16;ww++){ const float* pp = smf + FPSUM + ww*384 + m*3; \
            r0+=pp[0]; r1+=pp[1]; r2+=pp[2]; } } while(0)

#pragma unroll 1
    for (int s = 0; s < NSTEPS; s++){
        if (!__syncthreads_or(off != 0.0f)) break;

        // ---- fwd1 ----
        LAYER1_STAGE(px, py, pz, tt);
        __syncthreads();
        gemm_epi<0>(smf, sb, lane, tig, g, wslot, bhh, g2p, b2r, w3r);
        __syncthreads();
        float dt = copysignf(fminf(fabsf(off), DT_MAXF), off);
        float v0,v1,v2; SUM3(v0,v1,v2);
        float qx = fmaf(-0.5f*dt, v0+b3x, px);
        float qy = fmaf(-0.5f*dt, v1+b3y, py);
        float qz = fmaf(-0.5f*dt, v2+b3z, pz);
        float qt = tt - 0.5f*dt;

        // ---- fwd2 (captures g2 fragments) ----
        LAYER1_STAGE(qx, qy, qz, qt);
        __syncthreads();
        gemm_epi<1>(smf, sb, lane, tig, g, wslot, bhh, g2p, b2r, w3r);
        __syncthreads();
        float vx,vy,vz; SUM3(vx,vy,vz);
        vx+=b3x; vy+=b3y; vz+=b3z;
        // h -> g1
#pragma unroll
        for (int i=0;i<32;i++) h[i] = fmaf(-h[i], h[i], 1.f);

        // ---- tangents ----
        float jac[9];
#pragma unroll 1
        for (int j=0;j<3;j++){
            STAGE_TAN(j);
            __syncthreads();
            gemm_epi<2>(smf, sb, lane, tig, g, wslot, bhh, g2p, b2r, w3r);
            __syncthreads();
            SUM3(jac[j*3+0], jac[j*3+1], jac[j*3+2]);
        }

        float dr[9];
#pragma unroll
        for (int o=0;o<3;o++)
#pragma unroll
            for (int c=0;c<3;c++)
                dr[o*3+c] = jac[0+o]*D[0*3+c] + jac[3+o]*D[1*3+c] + jac[6+o]*D[2*3+c];
#pragma unroll
        for (int q=0;q<9;q++) D[q] = fmaf(-dt, dr[q], D[q]);
        px = fmaf(-dt, vx, px);
        py = fmaf(-dt, vy, py);
        pz = fmaf(-dt, vz, pz);
        tt -= dt; off -= dt;
    }

    if (kq == 0 && myp >= 0){
        out[(size_t)myp*3+0]=px; out[(size_t)myp*3+1]=py; out[(size_t)myp*3+2]=pz;
        float* od = out + (size_t)n*3 + (size_t)myp*9;
#pragma unroll
        for (int q=0;q<9;q++) od[q] = D[q];
    }
}

extern "C" void kernel_launch(void* const* d_in, const int* in_sizes, int n_in,
                              void* d_out, int out_size)
{
    const float* code = (const float*)d_in[0];
    const float* pos  = (const float*)d_in[1];
    const float* t1   = (const float*)d_in[2];
    const float* t2   = (const float*)d_in[3];
    const float* W1   = (const float*)d_in[4];
    const float* b1   = (const float*)d_in[5];
    const float* W2   = (const float*)d_in[6];
    const float* b2   = (const float*)d_in[7];
    const float* W3   = (const float*)d_in[8];
    const float* b3   = (const float*)d_in[9];
    const int n = in_sizes[2];
    const int nb = (n + 255)/256;

    k_hist<<<nb,256>>>(t1,t2,n);
    k_prefix<<<1,32>>>(nb);
    k_scatter<<<nb,256>>>(t1,t2,n);

    cudaFuncSetAttribute(velwarp_kernel,
                         cudaFuncAttributeMaxDynamicSharedMemorySize, SMEM_BYTES);
    velwarp_kernel<<<(n+127)/128, THREADS, SMEM_BYTES>>>(
        code, pos, t1, t2, W1, b1, W2, b2, W3, b3, (float*)d_out, n);
}

// round 12
// speedup vs baseline: 1.6325x; 1.6325x over previous
#include <cuda_runtime.h>
#include <cuda_fp16.h>
#include <cstdint>

#define HID 128
#define DT_MAXF 0.125f
#define NSTEPS 8
#define THREADS 256
#define MAXN (1<<18)
#define APITCH 272              // bytes per A row (128 fp16 + pad)

__device__ int g_parts[1024][16];
__device__ int g_cursor[16];
__device__ int g_perm[MAXN];

// ---- smem byte offsets ----
#define OFF_A0HI 0              // 34816
#define OFF_A0LO 34816          // 34816
#define OFF_A1HI 69632          // 34816 (tangent buffer)
#define OFF_A1LO 104448         // 34816
#define OFF_CPRE 139264         // 65536: cpre f32 [k][m]
#define OFF_PSUM 204800         // 6144 : psum f32 [4 ngroups][128 m][3]
#define OFF_W1X  210944         // 2048 : f32 [k][4] = W1[64+q][k]
#define SMEM_BYTES 212992

#define FCPRE (OFF_CPRE/4)
#define FPSUM (OFF_PSUM/4)
#define FW1X  (OFF_W1X/4)

__device__ __forceinline__ float ftanh(float x){
    float e = __expf(2.0f*x);
    return 1.0f - __fdividef(2.0f, e+1.0f);
}
__device__ __forceinline__ uint32_t packh(float a, float b){
    __half2 t = __floats2half2_rn(a, b);
    return *reinterpret_cast<uint32_t*>(&t);
}
__device__ __forceinline__ void splith(float v, float& hi, float& lo){
    hi = __half2float(__float2half_rn(v));
    lo = v - hi;
}
__device__ __forceinline__ void mma16816(float d[4], const uint32_t a[4], const uint32_t b[2]){
    asm volatile(
        "mma.sync.aligned.m16n8k16.row.col.f32.f16.f16.f32 "
        "{%0,%1,%2,%3}, {%4,%5,%6,%7}, {%8,%9}, {%0,%1,%2,%3};"
        : "+f"(d[0]), "+f"(d[1]), "+f"(d[2]), "+f"(d[3])
        : "r"(a[0]), "r"(a[1]), "r"(a[2]), "r"(a[3]), "r"(b[0]), "r"(b[1]));
}
__device__ __forceinline__ void ldmat4(uint32_t a[4], uint32_t addr){
    asm volatile("ldmatrix.sync.aligned.m8n8.x4.shared.b16 {%0,%1,%2,%3}, [%4];"
        : "=r"(a[0]), "=r"(a[1]), "=r"(a[2]), "=r"(a[3]) : "r"(addr) : "memory");
}

// One GEMM phase + fused epilogue. Warp tile: 64 rows (mg) x 32 cols (ng).
// 2-term fp16 split (Ahi*Bhi + Alo*Bhi), fp32 accum, 4 independent nt chains.
// MODE 0: tanh(d+b2)*W3 -> psum ; MODE 1: + capture g2 ; MODE 2: (d*g2)*W3 -> psum
template<int MODE>
__device__ __forceinline__ void gemm_epi(float* smf, uint32_t sb, uint32_t aoff,
        int lane, int tig, int g, int mg, int ng,
        const uint32_t (&bhh)[4][8][2], uint32_t (&g2p)[4][4][2],
        const float (&b2r)[4][2], const float (&w3r)[4][2][3])
{
    const uint32_t arow0 = sb + aoff + (uint32_t)(mg*64 + (lane & 15))*APITCH
                         + ((lane & 16) ? 16u : 0u);
#pragma unroll
    for (int mt = 0; mt < 4; mt++){
        uint32_t ab = arow0 + (uint32_t)(mt*16)*APITCH;
        float d[4][4];
#pragma unroll
        for (int nt=0;nt<4;nt++){ d[nt][0]=0.f; d[nt][1]=0.f; d[nt][2]=0.f; d[nt][3]=0.f; }
#pragma unroll
        for (int kt = 0; kt < 8; kt++){
            uint32_t ah[4], al[4];
            ldmat4(ah, ab + kt*32);
            ldmat4(al, ab + 34816u + kt*32);
#pragma unroll
            for (int nt = 0; nt < 4; nt++){
                mma16816(d[nt], ah, bhh[nt][kt]);
                mma16816(d[nt], al, bhh[nt][kt]);
            }
        }
        float s[2][3] = {{0.f,0.f,0.f},{0.f,0.f,0.f}};
#pragma unroll
        for (int nt = 0; nt < 4; nt++){
#pragma unroll
            for (int rh = 0; rh < 2; rh++){
                float g2v[2] = {0.f, 0.f};
                if (MODE == 2){
                    uint32_t u = g2p[mt][nt][rh];
                    __half2 hv2 = *reinterpret_cast<__half2*>(&u);
                    g2v[0] = __low2float(hv2); g2v[1] = __high2float(hv2);
                }
                float ng2[2] = {0.f, 0.f};
#pragma unroll
                for (int cj = 0; cj < 2; cj++){
                    float val = d[nt][rh*2 + cj];
                    float use;
                    if (MODE < 2){
                        float hv = ftanh(val + b2r[nt][cj]);
                        if (MODE == 1) ng2[cj] = fmaf(-hv, hv, 1.f);
                        use = hv;
                    } else {
                        use = val * g2v[cj];
                    }
                    s[rh][0] = fmaf(use, w3r[nt][cj][0], s[rh][0]);
                    s[rh][1] = fmaf(use, w3r[nt][cj][1], s[rh][1]);
                    s[rh][2] = fmaf(use, w3r[nt][cj][2], s[rh][2]);
                }
                if (MODE == 1){
                    __half2 p = __floats2half2_rn(ng2[0], ng2[1]);
                    g2p[mt][nt][rh] = *reinterpret_cast<uint32_t*>(&p);
                }
            }
        }
#pragma unroll
        for (int rh = 0; rh < 2; rh++)
#pragma unroll
        for (int o = 0; o < 3; o++){
            float v = s[rh][o];
            v += __shfl_xor_sync(0xffffffffu, v, 1);
            v += __shfl_xor_sync(0xffffffffu, v, 2);
            s[rh][o] = v;
        }
        if (tig == 0){
            int row0 = mg*64 + mt*16 + g;
            float* p0 = smf + FPSUM + ng*384 + row0*3;
            p0[0]=s[0][0]; p0[1]=s[0][1]; p0[2]=s[0][2];
            float* p1 = p0 + 8*3;
            p1[0]=s[1][0]; p1[1]=s[1][1]; p1[2]=s[1][2];
        }
    }
}

// ---- bucketing: 3 kernels ----
__device__ __forceinline__ int steps_needed(float off){
    float a = fabsf(off);
    int k = (int)ceilf(a*8.0f);
    return k > NSTEPS ? NSTEPS : k;
}
__global__ void k_hist(const float* t1, const float* t2, int n){
    __shared__ int lh[16];
    if (threadIdx.x < 16) lh[threadIdx.x] = 0;
    __syncthreads();
    int i = blockIdx.x*blockDim.x + threadIdx.x;
    if (i < n) atomicAdd(&lh[steps_needed(t1[i]-t2[i])], 1);
    __syncthreads();
    if (threadIdx.x < 16) g_parts[blockIdx.x][threadIdx.x] = lh[threadIdx.x];
}
__global__ void k_prefix(int nb){
    __shared__ int tot[16];
    int b = threadIdx.x;
    if (b < 16){
        int s = 0;
        for (int blk = 0; blk < nb; blk++) s += g_parts[blk][b];
        tot[b] = s;
    }
    __syncthreads();
    if (threadIdx.x == 0){
        int s = 0;
#pragma unroll
        for (int q = 0; q <= NSTEPS; q++){ g_cursor[q] = s; s += tot[q]; }
    }
}
__global__ void k_scatter(const float* t1, const float* t2, int n){
    __shared__ int lh[16], lb[16];
    if (threadIdx.x < 16) lh[threadIdx.x] = 0;
    __syncthreads();
    int i = blockIdx.x*blockDim.x + threadIdx.x;
    int k = 0, loc = 0; bool v = (i < n);
    if (v){ k = steps_needed(t1[i]-t2[i]); loc = atomicAdd(&lh[k], 1); }
    __syncthreads();
    if (threadIdx.x < 16 && lh[threadIdx.x])
        lb[threadIdx.x] = atomicAdd(&g_cursor[threadIdx.x], lh[threadIdx.x]);
    __syncthreads();
    if (v) g_perm[lb[k]+loc] = i;
}

__global__ void __launch_bounds__(THREADS, 1)
velwarp_kernel(const float* __restrict__ code_g, const float* __restrict__ pos_g,
               const float* __restrict__ t1_g, const float* __restrict__ t2_g,
               const float* __restrict__ W1_g, const float* __restrict__ b1_g,
               const float* __restrict__ W2_g, const float* __restrict__ b2_g,
               const float* __restrict__ W3_g, const float* __restrict__ b3_g,
               float* __restrict__ out, int n)
{
    extern __shared__ char smc[];
    float* smf = (float*)smc;
    uint32_t sb;
    asm("{ .reg .u64 t; cvta.to.shared.u64 t, %1; cvt.u32.u64 %0, t; }" : "=r"(sb) : "l"(smc));

    const int tid  = threadIdx.x;
    const int lane = tid & 31;
    const int g    = lane >> 2;
    const int tig  = lane & 3;
    const int wslot = tid >> 5;          // 0..7
    const int mg   = wslot >> 2;         // m group: rows [mg*64, +64)
    const int ng   = wslot & 3;          // n group: cols [ng*32, +32)
    const int m    = tid & 127;          // point in CTA
    const int kh   = tid >> 7;           // k half 0..1 (64 k's each)
    const int pbase = blockIdx.x * 128;
    const int slot = pbase + m;
    const int myp = (slot < n) ? g_perm[slot] : -1;

    // ---- prologue: W1 staged temporarily into A0 region; cpre -> smem ----
    {
        float* w1tmp = (float*)(smc + OFF_A0HI);
        for (int i = tid; i < 64*HID; i += THREADS) w1tmp[i] = W1_g[i];
        if (tid < HID){
#pragma unroll
            for (int kk=0;kk<4;kk++) smf[FW1X + tid*4 + kk] = W1_g[(64+kk)*HID + tid];
        }
        __syncthreads();
        float acc[64];
#pragma unroll
        for (int i=0;i<64;i++) acc[i] = b1_g[kh*64 + i];
#pragma unroll 1
        for (int c0=0;c0<64;c0+=16){
            float cd[16];
#pragma unroll
            for (int u=0;u<16;u++)
                cd[u] = (myp>=0) ? code_g[(size_t)myp*64 + c0 + u] : 0.f;
#pragma unroll
            for (int u=0;u<16;u++){
                float cc = cd[u];
                const float* wr = w1tmp + (c0+u)*HID + kh*64;
#pragma unroll
                for (int i=0;i<64;i+=4){
                    float4 w = *(const float4*)(wr + i);
                    acc[i]   = fmaf(cc,w.x,acc[i]);
                    acc[i+1] = fmaf(cc,w.y,acc[i+1]);
                    acc[i+2] = fmaf(cc,w.z,acc[i+2]);
                    acc[i+3] = fmaf(cc,w.w,acc[i+3]);
                }
            }
        }
        __syncthreads();   // done reading w1tmp
#pragma unroll
        for (int i=0;i<64;i++) smf[FCPRE + (kh*64+i)*128 + m] = acc[i];
        __syncthreads();
    }

    // ---- W2 hi fragments (fp16) in registers: this warp's 32 cols ----
    uint32_t bhh[4][8][2];
#pragma unroll
    for (int nt=0;nt<4;nt++)
#pragma unroll
    for (int kt=0;kt<8;kt++){
        int nn = ng*32 + nt*8 + g;
        int k0 = kt*16 + tig*2;
        float f0=W2_g[(size_t)k0*HID+nn],     f1=W2_g[(size_t)(k0+1)*HID+nn];
        float f2=W2_g[(size_t)(k0+8)*HID+nn], f3=W2_g[(size_t)(k0+9)*HID+nn];
        bhh[nt][kt][0]=packh(f0,f1); bhh[nt][kt][1]=packh(f2,f3);
    }
    float b2r[4][2], w3r[4][2][3];
#pragma unroll
    for (int nt=0;nt<4;nt++)
#pragma unroll
    for (int cj=0;cj<2;cj++){
        int nn = ng*32 + nt*8 + tig*2 + cj;
        b2r[nt][cj] = b2_g[nn];
        w3r[nt][cj][0]=W3_g[nn*3+0]; w3r[nt][cj][1]=W3_g[nn*3+1]; w3r[nt][cj][2]=W3_g[nn*3+2];
    }
    const float b3x=b3_g[0], b3y=b3_g[1], b3z=b3_g[2];

    // ---- ODE state replicated in both kh threads per point ----
    float px=0.f,py=0.f,pz=0.f,tt=0.f,off=0.f;
    float D[9] = {1,0,0, 0,1,0, 0,0,1};
    if (myp>=0){
        px = pos_g[(size_t)myp*3+0];
        py = pos_g[(size_t)myp*3+1];
        pz = pos_g[(size_t)myp*3+2];
        tt = t1_g[myp];
        off = tt - t2_g[myp];
    }

    uint32_t g2p[4][4][2];

    // fwd stage: thread (m, kh) computes 64 h values, splits, writes A0
#define LAYER1_STAGE(X0,X1,X2,X3) do { \
        _Pragma("unroll") \
        for (int i2=0;i2<8;i2++){ \
            uint32_t hi4[4], lo4[4]; \
            _Pragma("unroll") \
            for (int u2=0;u2<4;u2++){ \
                int k0 = kh*64 + i2*8 + u2*2; \
                float a0 = smf[FCPRE + k0*128 + m]; \
                float a1 = smf[FCPRE + (k0+1)*128 + m]; \
                float4 w0 = *(const float4*)(smf + FW1X + k0*4); \
                float4 w1 = *(const float4*)(smf + FW1X + (k0+1)*4); \
                a0=fmaf((X0),w0.x,a0); a0=fmaf((X1),w0.y,a0); a0=fmaf((X2),w0.z,a0); a0=fmaf((X3),w0.w,a0); \
                a1=fmaf((X0),w1.x,a1); a1=fmaf((X1),w1.y,a1); a1=fmaf((X2),w1.z,a1); a1=fmaf((X3),w1.w,a1); \
                float hv0=ftanh(a0), hv1=ftanh(a1); \
                float ha,la,hb,lb; splith(hv0,ha,la); splith(hv1,hb,lb); \
                hi4[u2]=packh(ha,hb); lo4[u2]=packh(la,lb); \
            } \
            *(uint4*)(smc + OFF_A0HI + m*APITCH + (kh*64+i2*8)*2) = make_uint4(hi4[0],hi4[1],hi4[2],hi4[3]); \
            *(uint4*)(smc + OFF_A0LO + m*APITCH + (kh*64+i2*8)*2) = make_uint4(lo4[0],lo4[1],lo4[2],lo4[3]); \
        } \
    } while(0)

    // tangent stage: reconstruct h1 from A0 (hi+lo), dh = (1-h^2)*w1x_j -> A1
#define STAGE_TAN(J) do { \
        _Pragma("unroll") \
        for (int i2=0;i2<8;i2++){ \
            uint4 hu = *(const uint4*)(smc + OFF_A0HI + m*APITCH + (kh*64+i2*8)*2); \
            uint4 lu = *(const uint4*)(smc + OFF_A0LO + m*APITCH + (kh*64+i2*8)*2); \
            uint32_t hw[4]={hu.x,hu.y,hu.z,hu.w}, lw[4]={lu.x,lu.y,lu.z,lu.w}; \
            uint32_t hi4[4], lo4[4]; \
            _Pragma("unroll") \
            for (int u2=0;u2<4;u2++){ \
                int k0 = kh*64 + i2*8 + u2*2; \
                __half2 hh = *reinterpret_cast<__half2*>(&hw[u2]); \
                __half2 ll = *reinterpret_cast<__half2*>(&lw[u2]); \
                float h0 = __low2float(hh) + __low2float(ll); \
                float h1 = __high2float(hh) + __high2float(ll); \
                float v0 = fmaf(-h0,h0,1.f) * smf[FW1X + k0*4 + (J)]; \
                float v1 = fmaf(-h1,h1,1.f) * smf[FW1X + (k0+1)*4 + (J)]; \
                float ha,la,hb,lb; splith(v0,ha,la); splith(v1,hb,lb); \
                hi4[u2]=packh(ha,hb); lo4[u2]=packh(la,lb); \
            } \
            *(uint4*)(smc + OFF_A1HI + m*APITCH + (kh*64+i2*8)*2) = make_uint4(hi4[0],hi4[1],hi4[2],hi4[3]); \
            *(uint4*)(smc + OFF_A1LO + m*APITCH + (kh*64+i2*8)*2) = make_uint4(lo4[0],lo4[1],lo4[2],lo4[3]); \
        } \
    } while(0)

#define SUM3(r0,r1,r2) do { r0=0.f;r1=0.f;r2=0.f; \
        _Pragma("unroll") \
        for (int gg=0;gg<4;gg++){ const float* pp = smf + FPSUM + gg*384 + m*3; \
            r0+=pp[0]; r1+=pp[1]; r2+=pp[2]; } } while(0)

#pragma unroll 1
    for (int s = 0; s < NSTEPS; s++){
        if (!__syncthreads_or(off != 0.0f)) break;

        // ---- fwd1 ----
        LAYER1_STAGE(px, py, pz, tt);
        __syncthreads();
        gemm_epi<0>(smf, sb, OFF_A0HI, lane, tig, g, mg, ng, bhh, g2p, b2r, w3r);
        __syncthreads();
        float dt = copysignf(fminf(fabsf(off), DT_MAXF), off);
        float v0,v1,v2; SUM3(v0,v1,v2);
        float qx = fmaf(-0.5f*dt, v0+b3x, px);
        float qy = fmaf(-0.5f*dt, v1+b3y, py);
        float qz = fmaf(-0.5f*dt, v2+b3z, pz);
        float qt = tt - 0.5f*dt;

        // ---- fwd2 (captures g2) ----
        LAYER1_STAGE(qx, qy, qz, qt);
        __syncthreads();
        gemm_epi<1>(smf, sb, OFF_A0HI, lane, tig, g, mg, ng, bhh, g2p, b2r, w3r);
        __syncthreads();
        float vx,vy,vz; SUM3(vx,vy,vz);
        vx+=b3x; vy+=b3y; vz+=b3z;

        // ---- tangents (read h1 from A0, stage into A1) ----
        float jac[9];
#pragma unroll 1
        for (int j=0;j<3;j++){
            STAGE_TAN(j);
            __syncthreads();
            gemm_epi<2>(smf, sb, OFF_A1HI, lane, tig, g, mg, ng, bhh, g2p, b2r, w3r);
            __syncthreads();
            SUM3(jac[j*3+0], jac[j*3+1], jac[j*3+2]);
        }

        float dr[9];
#pragma unroll
        for (int o=0;o<3;o++)
#pragma unroll
            for (int c=0;c<3;c++)
                dr[o*3+c] = jac[0+o]*D[0*3+c] + jac[3+o]*D[1*3+c] + jac[6+o]*D[2*3+c];
#pragma unroll
        for (int q=0;q<9;q++) D[q] = fmaf(-dt, dr[q], D[q]);
        px = fmaf(-dt, vx, px);
        py = fmaf(-dt, vy, py);
        pz = fmaf(-dt, vz, pz);
        tt -= dt; off -= dt;
    }

    if (kh == 0 && myp >= 0){
        out[(size_t)myp*3+0]=px; out[(size_t)myp*3+1]=py; out[(size_t)myp*3+2]=pz;
        float* od = out + (size_t)n*3 + (size_t)myp*9;
#pragma unroll
        for (int q=0;q<9;q++) od[q] = D[q];
    }
}

extern "C" void kernel_launch(void* const* d_in, const int* in_sizes, int n_in,
                              void* d_out, int out_size)
{
    const float* code = (const float*)d_in[0];
    const float* pos  = (const float*)d_in[1];
    const float* t1   = (const float*)d_in[2];
    const float* t2   = (const float*)d_in[3];
    const float* W1   = (const float*)d_in[4];
    const float* b1   = (const float*)d_in[5];
    const float* W2   = (const float*)d_in[6];
    const float* b2   = (const float*)d_in[7];
    const float* W3   = (const float*)d_in[8];
    const float* b3   = (const float*)d_in[9];
    const int n = in_sizes[2];
    const int nb = (n + 255)/256;

    k_hist<<<nb,256>>>(t1,t2,n);
    k_prefix<<<1,32>>>(nb);
    k_scatter<<<nb,256>>>(t1,t2,n);

    cudaFuncSetAttribute(velwarp_kernel,
                         cudaFuncAttributeMaxDynamicSharedMemorySize, SMEM_BYTES);
    velwarp_kernel<<<(n+127)/128, THREADS, SMEM_BYTES>>>(
        code, pos, t1, t2, W1, b1, W2, b2, W3, b3, (float*)d_out, n);
}